// round 7
// baseline (speedup 1.0000x reference)
#include <cuda_runtime.h>
#include <cuda_fp16.h>
#include <stdint.h>

#define TOKENS 256
#define IN_F   4096
#define OUT_F  11008
#define RANK   16
#define SCALINGF 2.0f

#define BM 128
#define BN 128
#define BK 64
#define KSPLIT 4
#define ITERS (IN_F / BK / KSPLIT)   // 16
#define THREADS 128

// stage: x 16KB + w 16KB
#define XH_OFF 0
#define WH_OFF 16384
#define STAGE_BYTES 32768
#define SMEM_DYN (2 * STAGE_BYTES + 1024)

__constant__ float c_nf4[16] = {
    -1.0f, -0.6961928009986877f, -0.5250730514526367f, -0.39491748809814453f,
    -0.28444138169288635f, -0.18477343022823334f, -0.09105003625154495f, 0.0f,
    0.07958029955625534f, 0.16093020141124725f, 0.24611230194568634f,
    0.33791524171829224f, 0.44070982933044434f, 0.5626170039176941f,
    0.7229568362236023f, 1.0f
};

__device__ float g_u[TOKENS * RANK];
__device__ __align__(16) __half g_xh[TOKENS * IN_F];
__device__ float g_part[KSPLIT * TOKENS * OUT_F];   // 45 MB scratch

// ------------------------------------------------------------------ helpers
__device__ __forceinline__ uint32_t smem_u32(const void* p) {
    uint32_t a;
    asm("{ .reg .u64 t; cvta.to.shared.u64 t, %1; cvt.u32.u64 %0, t; }"
        : "=r"(a) : "l"(p));
    return a;
}

__device__ __forceinline__ uint32_t sw128(uint32_t o) {
    return o ^ ((o >> 3) & 0x70);
}

__device__ __forceinline__ void cp16(uint32_t dst, const void* src) {
    asm volatile("cp.async.cg.shared.global [%0], [%1], 16;"
                 :: "r"(dst), "l"(src) : "memory");
}
__device__ __forceinline__ void cp_commit() {
    asm volatile("cp.async.commit_group;" ::: "memory");
}
__device__ __forceinline__ void cp_wait0() {
    asm volatile("cp.async.wait_group 0;" ::: "memory");
}

__device__ __forceinline__ void ldsm4(uint32_t* r, uint32_t addr) {
    asm volatile("ldmatrix.sync.aligned.m8n8.x4.shared.b16 {%0,%1,%2,%3}, [%4];"
                 : "=r"(r[0]), "=r"(r[1]), "=r"(r[2]), "=r"(r[3]) : "r"(addr));
}

__device__ __forceinline__ void mma16816(float* c, const uint32_t* a,
                                         const uint32_t* b) {
    asm volatile(
        "mma.sync.aligned.m16n8k16.row.col.f32.f16.f16.f32 "
        "{%0,%1,%2,%3},{%4,%5,%6,%7},{%8,%9},{%0,%1,%2,%3};"
        : "+f"(c[0]), "+f"(c[1]), "+f"(c[2]), "+f"(c[3])
        : "r"(a[0]), "r"(a[1]), "r"(a[2]), "r"(a[3]), "r"(b[0]), "r"(b[1]));
}

__device__ __forceinline__ uint32_t pack_f16x2(float a, float b) {
    uint32_t d;
    asm("cvt.rn.f16x2.f32 %0, %1, %2;" : "=r"(d) : "f"(b), "f"(a));
    return d;
}

__device__ __forceinline__ float dot16(const float* a, const float* b) {
    float s = 0.0f;
#pragma unroll
    for (int v = 0; v < 4; ++v) {
        float4 x = ((const float4*)a)[v];
        float4 y = ((const float4*)b)[v];
        s += x.x * y.x + x.y * y.y + x.z * y.z + x.w * y.w;
    }
    return s;
}

// ------------------------------------------------------------------ prep
__global__ void prep_kernel(const float* __restrict__ x,
                            const float* __restrict__ A) {
    const int t = blockIdx.x;
    const int tid = threadIdx.x;

    float acc[RANK];
#pragma unroll
    for (int r = 0; r < RANK; r++) acc[r] = 0.0f;

    const float* xr = x + (size_t)t * IN_F;
    for (int k = tid; k < IN_F; k += 256) {
        float xv = xr[k];
        g_xh[t * IN_F + k] = __float2half_rn(xv);
#pragma unroll
        for (int r = 0; r < RANK; r++)
            acc[r] += xv * A[r * IN_F + k];
    }

    __shared__ float red[RANK];
    if (tid < RANK) red[tid] = 0.0f;
    __syncthreads();
#pragma unroll
    for (int r = 0; r < RANK; r++) {
        float v = acc[r];
#pragma unroll
        for (int off = 16; off > 0; off >>= 1)
            v += __shfl_down_sync(0xFFFFFFFFu, v, off);
        if ((tid & 31) == 0) atomicAdd(&red[r], v);
    }
    __syncthreads();
    if (tid < RANK) g_u[t * RANK + tid] = red[tid] * SCALINGF;
}

// ------------------------------------------------------------------ main
extern __shared__ char dynsmem[];

__global__ __launch_bounds__(THREADS, 2)
void lora4bit_fp16_kernel(const int* __restrict__ q,
                          const float* __restrict__ absmax) {
    __shared__ float lut[16];

    const int tid  = threadIdx.x;
    const int wid  = tid >> 5;
    const int lane = tid & 31;
    const int bn = blockIdx.x * BN;
    const int bm = blockIdx.y * BM;
    const int kz = blockIdx.z;                 // k split index
    const int kbase = kz * (IN_F / KSPLIT);    // 1024 * kz

    const uint32_t dbase = (smem_u32(dynsmem) + 1023u) & ~1023u;
    char* dptr = dynsmem + (dbase - smem_u32(dynsmem));

    if (tid < 16) lut[tid] = c_nf4[tid];

    // ---- producer mapping: one row per thread for both tiles
    const int*   qptr  = q + (size_t)(bn + tid) * IN_F + kbase;
    const float* amptr = absmax + (size_t)(bn + tid) * (IN_F / 64) + kz * ITERS;
    const __half* xptr = g_xh + (size_t)(bm + tid) * IN_F + kbase;

    // ---- prologue: codes for it=0, cp.async x stage 0
    int4 qreg[16];
    {
        const int4* p = (const int4*)qptr;
#pragma unroll
        for (int v = 0; v < 16; ++v) qreg[v] = p[v];
    }
    float scale_cur = amptr[0];

    {
#pragma unroll
        for (int c = 0; c < 8; ++c) {
            uint32_t off = sw128((uint32_t)(tid * 128 + c * 16));
            cp16(dbase + XH_OFF + off, xptr + c * 8);
        }
        cp_commit();
    }
    __syncthreads();   // lut visible

    // ---- mma lane mapping (warp tile 64x64, warps 2x2)
    const int wm = (wid & 1) * 64;
    const int wn = (wid >> 1) * 64;
    const int am_r = (lane & 7) + ((lane >> 3) & 1) * 8;
    const int a_kb = (lane >> 4) * 16;
    const int b_nr = (lane & 7) + ((lane >> 4) & 1) * 8;
    const int b_kb = ((lane >> 3) & 1) * 16;

    float acc[4][8][4];
#pragma unroll
    for (int i = 0; i < 4; ++i)
#pragma unroll
        for (int j = 0; j < 8; ++j)
#pragma unroll
            for (int e = 0; e < 4; ++e) acc[i][j][e] = 0.0f;

    for (int it = 0; it < ITERS; ++it) {
        const int s = it & 1;
        const uint32_t stg = dbase + s * STAGE_BYTES;
        char* stgp = dptr + s * STAGE_BYTES;

        cp_wait0();   // x tile of stage s arrived

        // ---- dequant: 64 codes (this thread's W row) -> fp16 into stage s
        {
            float s0 = scale_cur;
#pragma unroll
            for (int g = 0; g < 8; ++g) {
                uint4 hib;
                uint32_t* hp = &hib.x;
#pragma unroll
                for (int p = 0; p < 2; ++p) {
                    int4 qq = qreg[g * 2 + p];
                    int cs[4] = {qq.x, qq.y, qq.z, qq.w};
#pragma unroll
                    for (int j = 0; j < 2; ++j) {
                        float w0 = lut[cs[j * 2] & 15] * s0;
                        float w1 = lut[cs[j * 2 + 1] & 15] * s0;
                        hp[p * 2 + j] = pack_f16x2(w0, w1);
                    }
                }
                uint32_t off = sw128((uint32_t)(tid * 128 + g * 16));
                *(uint4*)(stgp + WH_OFF + off) = hib;
            }
        }
        __syncthreads();   // W visible; stage s^1 consumers done

        // ---- prefetch next iter: codes->regs, x->stage s^1
        if (it + 1 < ITERS) {
            const int4* p = (const int4*)(qptr + (it + 1) * BK);
#pragma unroll
            for (int v = 0; v < 16; ++v) qreg[v] = p[v];
            scale_cur = amptr[it + 1];

            uint32_t st = dbase + (s ^ 1) * STAGE_BYTES;
            const __half* xs = xptr + (it + 1) * BK;
#pragma unroll
            for (int c = 0; c < 8; ++c) {
                uint32_t off = sw128((uint32_t)(tid * 128 + c * 16));
                cp16(st + XH_OFF + off, xs + c * 8);
            }
            cp_commit();
        }

        // ---- compute on stage s
#pragma unroll
        for (int ks = 0; ks < 4; ++ks) {
            uint32_t ah[4][4];
#pragma unroll
            for (int mi = 0; mi < 4; ++mi) {
                uint32_t off = sw128(
                    (uint32_t)((wm + mi * 16 + am_r) * 128 + ks * 32 + a_kb));
                ldsm4(ah[mi], stg + XH_OFF + off);
            }
            uint32_t bh[8][2];
#pragma unroll
            for (int jp = 0; jp < 4; ++jp) {
                uint32_t off = sw128(
                    (uint32_t)((wn + jp * 16 + b_nr) * 128 + ks * 32 + b_kb));
                uint32_t t[4];
                ldsm4(t, stg + WH_OFF + off);
                bh[jp * 2][0] = t[0]; bh[jp * 2][1] = t[1];
                bh[jp * 2 + 1][0] = t[2]; bh[jp * 2 + 1][1] = t[3];
            }
#pragma unroll
            for (int mi = 0; mi < 4; ++mi)
#pragma unroll
                for (int nj = 0; nj < 8; ++nj)
                    mma16816(acc[mi][nj], ah[mi], bh[nj]);
        }
    }

    // ---- store fp32 partial tile
    float* pbase = g_part + (size_t)kz * TOKENS * OUT_F;
#pragma unroll
    for (int mi = 0; mi < 4; ++mi) {
        const int r0 = wm + mi * 16 + (lane >> 2);
        const int r1 = r0 + 8;
        float* p0 = pbase + (size_t)(bm + r0) * OUT_F + bn;
        float* p1 = pbase + (size_t)(bm + r1) * OUT_F + bn;
#pragma unroll
        for (int nj = 0; nj < 8; ++nj) {
            const int c0 = wn + nj * 8 + (lane & 3) * 2;
            *(float2*)(p0 + c0) = make_float2(acc[mi][nj][0], acc[mi][nj][1]);
            *(float2*)(p1 + c0) = make_float2(acc[mi][nj][2], acc[mi][nj][3]);
        }
    }
}

// ------------------------------------------------------------------ reduce
__global__ __launch_bounds__(256)
void reduce_kernel(const float* __restrict__ lora_B,
                   float* __restrict__ out) {
    const int gid = blockIdx.x * 256 + threadIdx.x;
    const int nquads = OUT_F / 4;                 // 2752
    if (gid >= TOKENS * nquads) return;
    const int t = gid / nquads;
    const int o = (gid % nquads) * 4;

    float4 s = *(const float4*)(g_part + (size_t)t * OUT_F + o);
#pragma unroll
    for (int z = 1; z < KSPLIT; ++z) {
        float4 p = *(const float4*)(g_part + (size_t)z * TOKENS * OUT_F +
                                    (size_t)t * OUT_F + o);
        s.x += p.x; s.y += p.y; s.z += p.z; s.w += p.w;
    }

    float u[RANK];
#pragma unroll
    for (int v = 0; v < 4; ++v)
        ((float4*)u)[v] = ((const float4*)(g_u + t * RANK))[v];

    s.x += dot16(u, lora_B + (size_t)(o + 0) * RANK);
    s.y += dot16(u, lora_B + (size_t)(o + 1) * RANK);
    s.z += dot16(u, lora_B + (size_t)(o + 2) * RANK);
    s.w += dot16(u, lora_B + (size_t)(o + 3) * RANK);

    *(float4*)(out + (size_t)t * OUT_F + o) = s;
}

// ------------------------------------------------------------------ launch
extern "C" void kernel_launch(void* const* d_in, const int* in_sizes, int n_in,
                              void* d_out, int out_size) {
    const float* x      = (const float*)d_in[0];
    const int*   q      = (const int*)  d_in[1];
    const float* absmax = (const float*)d_in[2];
    const float* lora_A = (const float*)d_in[3];
    const float* lora_B = (const float*)d_in[4];
    float* out = (float*)d_out;

    cudaFuncSetAttribute(lora4bit_fp16_kernel,
                         cudaFuncAttributeMaxDynamicSharedMemorySize, SMEM_DYN);

    prep_kernel<<<TOKENS, 256>>>(x, lora_A);

    dim3 grid(OUT_F / BN, TOKENS / BM, KSPLIT);   // (86, 2, 4) = 688
    lora4bit_fp16_kernel<<<grid, THREADS, SMEM_DYN>>>(q, absmax);

    const int total = TOKENS * (OUT_F / 4);
    reduce_kernel<<<(total + 255) / 256, 256>>>(lora_B, out);
}